// round 1
// baseline (speedup 1.0000x reference)
#include <cuda_runtime.h>
#include <math.h>
#include <stdint.h>

// ---------------- problem constants ----------------
#define BT      8
#define SEQ     576
#define MTOT    (BT * SEQ)        // 4608
#define NLF     25                // layers in features
#define DIM     2048              // D
#define CTD     1024              // CT
#define NLAYER  7
#define HEADS   8
#define HDIM    128
#define ATT_SCALE 0.03125f        // CT^-0.5 = 1/32
#define LN_EPSF   1e-5f
#define COS_EPSF  1e-8f

// LAYER_IDX[l] = 24 - 4*l

// ---------------- device scratch (no allocations allowed) ----------------
__device__ float g_xn[(size_t)NLAYER * MTOT * DIM];   // layernormed slices, per-layer contiguous
__device__ float g_v[(size_t)MTOT * 8 * CTD];         // slots 0..6 = vout layers, slot 7 = vin
__device__ float g_fuse[(size_t)MTOT * CTD];
__device__ float g_vf[(size_t)MTOT * CTD];
__device__ float g_cos[MTOT];

// ---------------- helpers ----------------
__device__ __forceinline__ float warp_sum(float v) {
#pragma unroll
    for (int o = 16; o > 0; o >>= 1) v += __shfl_xor_sync(0xffffffffu, v, o);
    return v;
}

// ---------------- 1) gather + layernorm ----------------
// grid: MTOT*NLAYER blocks, 256 threads. Each block: one (m, l) row of 2048.
__global__ void __launch_bounds__(256) ln_kernel(
    const float* __restrict__ features,
    const float* __restrict__ ln_scale,
    const float* __restrict__ ln_bias)
{
    int l = blockIdx.x % NLAYER;
    int m = blockIdx.x / NLAYER;
    int layer = 24 - 4 * l;
    const float4* x = reinterpret_cast<const float4*>(
        features + ((size_t)m * NLF + layer) * DIM);
    int t = threadIdx.x;

    float4 a = x[t];
    float4 b = x[t + 256];
    float s  = a.x + a.y + a.z + a.w + b.x + b.y + b.z + b.w;
    float ss = a.x*a.x + a.y*a.y + a.z*a.z + a.w*a.w
             + b.x*b.x + b.y*b.y + b.z*b.z + b.w*b.w;

    __shared__ float shs[8], shss[8];
    float ws  = warp_sum(s);
    float wss = warp_sum(ss);
    int w = t >> 5, lane = t & 31;
    if (lane == 0) { shs[w] = ws; shss[w] = wss; }
    __syncthreads();
    float tot = 0.f, tot2 = 0.f;
#pragma unroll
    for (int i = 0; i < 8; i++) { tot += shs[i]; tot2 += shss[i]; }

    float mu  = tot * (1.0f / DIM);
    float var = tot2 * (1.0f / DIM) - mu * mu;
    float rs  = rsqrtf(var + LN_EPSF);

    const float4* sc = reinterpret_cast<const float4*>(ln_scale + (size_t)l * DIM);
    const float4* bi = reinterpret_cast<const float4*>(ln_bias  + (size_t)l * DIM);
    float4* o = reinterpret_cast<float4*>(g_xn + ((size_t)l * MTOT + m) * DIM);

    float4 s0 = sc[t],       b0 = bi[t];
    float4 s1 = sc[t + 256], b1 = bi[t + 256];
    float4 o0, o1;
    o0.x = (a.x - mu) * rs * s0.x + b0.x;
    o0.y = (a.y - mu) * rs * s0.y + b0.y;
    o0.z = (a.z - mu) * rs * s0.z + b0.z;
    o0.w = (a.w - mu) * rs * s0.w + b0.w;
    o1.x = (b.x - mu) * rs * s1.x + b1.x;
    o1.y = (b.y - mu) * rs * s1.y + b1.y;
    o1.z = (b.z - mu) * rs * s1.z + b1.z;
    o1.w = (b.w - mu) * rs * s1.w + b1.w;
    o[t] = o0;
    o[t + 256] = o1;
}

// ---------------- 2) batched GEMM: v slots ----------------
// grid (CTD/128, MTOT/128, 8). z<7: g_xn[z] @ w_norm[z]; z==7: features[:,:,24] @ w_in + b_in.
__global__ void __launch_bounds__(256) gemm1_kernel(
    const float* __restrict__ features,
    const float* __restrict__ w_norm,
    const float* __restrict__ w_in,
    const float* __restrict__ b_in)
{
    int z = blockIdx.z;
    const float* A;
    const float* B;
    const float* bias = nullptr;
    size_t lda;
    if (z < 7) {
        A = g_xn + (size_t)z * MTOT * DIM;
        lda = DIM;
        B = w_norm + (size_t)z * DIM * CTD;
    } else {
        A = features + 24 * DIM;          // row m at features + m*NLF*DIM + 24*DIM
        lda = (size_t)NLF * DIM;          // 51200
        B = w_in;
        bias = b_in;
    }
    const int K = DIM;

    int m0 = blockIdx.y * 128, n0 = blockIdx.x * 128;
    __shared__ float As[8][128];
    __shared__ float Bs[8][128];

    int tid  = threadIdx.x;
    int arow = tid >> 1, acol = (tid & 1) * 4;
    int brow = tid >> 5, bcol = (tid & 31) * 4;
    int ty   = tid >> 4, tx   = tid & 15;

    float acc[8][8];
#pragma unroll
    for (int i = 0; i < 8; i++)
#pragma unroll
        for (int j = 0; j < 8; j++) acc[i][j] = 0.f;

    for (int k0 = 0; k0 < K; k0 += 8) {
        float4 av = *reinterpret_cast<const float4*>(
            A + (size_t)(m0 + arow) * lda + k0 + acol);
        As[acol + 0][arow] = av.x;
        As[acol + 1][arow] = av.y;
        As[acol + 2][arow] = av.z;
        As[acol + 3][arow] = av.w;
        *reinterpret_cast<float4*>(&Bs[brow][bcol]) =
            *reinterpret_cast<const float4*>(B + (size_t)(k0 + brow) * CTD + n0 + bcol);
        __syncthreads();
#pragma unroll
        for (int k = 0; k < 8; k++) {
            float a[8], b[8];
            *reinterpret_cast<float4*>(&a[0]) = *reinterpret_cast<const float4*>(&As[k][ty * 8]);
            *reinterpret_cast<float4*>(&a[4]) = *reinterpret_cast<const float4*>(&As[k][ty * 8 + 4]);
            *reinterpret_cast<float4*>(&b[0]) = *reinterpret_cast<const float4*>(&Bs[k][tx * 8]);
            *reinterpret_cast<float4*>(&b[4]) = *reinterpret_cast<const float4*>(&Bs[k][tx * 8 + 4]);
#pragma unroll
            for (int i = 0; i < 8; i++)
#pragma unroll
                for (int j = 0; j < 8; j++) acc[i][j] += a[i] * b[j];
        }
        __syncthreads();
    }

    // epilogue: C row stride 8*CTD, slot offset z*CTD
    float* C = g_v + (size_t)z * CTD;
#pragma unroll
    for (int i = 0; i < 8; i++) {
        size_t row = (size_t)(m0 + ty * 8 + i);
        int n = n0 + tx * 8;
#pragma unroll
        for (int jj = 0; jj < 2; jj++) {
            float4 v;
            v.x = acc[i][jj * 4 + 0];
            v.y = acc[i][jj * 4 + 1];
            v.z = acc[i][jj * 4 + 2];
            v.w = acc[i][jj * 4 + 3];
            if (bias) {
                const float4 bb = *reinterpret_cast<const float4*>(bias + n + jj * 4);
                v.x += bb.x; v.y += bb.y; v.z += bb.z; v.w += bb.w;
            }
            *reinterpret_cast<float4*>(C + row * (8 * CTD) + n + jj * 4) = v;
        }
    }
}

// ---------------- 3) attention fuse ----------------
// grid MTOT blocks, 128 threads; thread t owns dim d=t of each head.
__global__ void __launch_bounds__(128) attn_kernel()
{
    int m = blockIdx.x, t = threadIdx.x;
    const float* vrow = g_v + (size_t)m * 8 * CTD;
    __shared__ float shp[6][4];
    __shared__ float slog[6];
    int w = t >> 5, lane = t & 31;

    for (int h = 0; h < HEADS; h++) {
        float q = vrow[h * HDIM + t] * ATT_SCALE;   // slot 0
        float kv[6];
#pragma unroll
        for (int l = 0; l < 6; l++)
            kv[l] = vrow[(size_t)(l + 1) * CTD + h * HDIM + t];
#pragma unroll
        for (int l = 0; l < 6; l++) {
            float p = warp_sum(q * kv[l]);
            if (lane == 0) shp[l][w] = p;
        }
        __syncthreads();
        if (t < 6) slog[t] = shp[t][0] + shp[t][1] + shp[t][2] + shp[t][3];
        __syncthreads();
        float mx = -1e30f;
#pragma unroll
        for (int l = 0; l < 6; l++) mx = fmaxf(mx, slog[l]);
        float e[6], sum = 0.f;
#pragma unroll
        for (int l = 0; l < 6; l++) { e[l] = expf(slog[l] - mx); sum += e[l]; }
        float inv = 1.0f / sum;
        float f = 0.f;
#pragma unroll
        for (int l = 0; l < 6; l++) f += (e[l] * inv) * kv[l];
        g_fuse[(size_t)m * CTD + h * HDIM + t] = f;
        __syncthreads();
    }
}

// ---------------- 4) GEMM2: vf = fuse @ w_out + vin + b_out ----------------
__global__ void __launch_bounds__(256) gemm2_kernel(
    const float* __restrict__ w_out,
    const float* __restrict__ b_out)
{
    const float* A = g_fuse;
    const float* B = w_out;
    const int K = CTD;

    int m0 = blockIdx.y * 128, n0 = blockIdx.x * 128;
    __shared__ float As[8][128];
    __shared__ float Bs[8][128];

    int tid  = threadIdx.x;
    int arow = tid >> 1, acol = (tid & 1) * 4;
    int brow = tid >> 5, bcol = (tid & 31) * 4;
    int ty   = tid >> 4, tx   = tid & 15;

    float acc[8][8];
#pragma unroll
    for (int i = 0; i < 8; i++)
#pragma unroll
        for (int j = 0; j < 8; j++) acc[i][j] = 0.f;

    for (int k0 = 0; k0 < K; k0 += 8) {
        float4 av = *reinterpret_cast<const float4*>(
            A + (size_t)(m0 + arow) * CTD + k0 + acol);
        As[acol + 0][arow] = av.x;
        As[acol + 1][arow] = av.y;
        As[acol + 2][arow] = av.z;
        As[acol + 3][arow] = av.w;
        *reinterpret_cast<float4*>(&Bs[brow][bcol]) =
            *reinterpret_cast<const float4*>(B + (size_t)(k0 + brow) * CTD + n0 + bcol);
        __syncthreads();
#pragma unroll
        for (int k = 0; k < 8; k++) {
            float a[8], b[8];
            *reinterpret_cast<float4*>(&a[0]) = *reinterpret_cast<const float4*>(&As[k][ty * 8]);
            *reinterpret_cast<float4*>(&a[4]) = *reinterpret_cast<const float4*>(&As[k][ty * 8 + 4]);
            *reinterpret_cast<float4*>(&b[0]) = *reinterpret_cast<const float4*>(&Bs[k][tx * 8]);
            *reinterpret_cast<float4*>(&b[4]) = *reinterpret_cast<const float4*>(&Bs[k][tx * 8 + 4]);
#pragma unroll
            for (int i = 0; i < 8; i++)
#pragma unroll
                for (int j = 0; j < 8; j++) acc[i][j] += a[i] * b[j];
        }
        __syncthreads();
    }

#pragma unroll
    for (int i = 0; i < 8; i++) {
        size_t row = (size_t)(m0 + ty * 8 + i);
        int n = n0 + tx * 8;
#pragma unroll
        for (int jj = 0; jj < 2; jj++) {
            float4 v;
            v.x = acc[i][jj * 4 + 0];
            v.y = acc[i][jj * 4 + 1];
            v.z = acc[i][jj * 4 + 2];
            v.w = acc[i][jj * 4 + 3];
            const float4 vin = *reinterpret_cast<const float4*>(
                g_v + row * (8 * CTD) + 7 * CTD + n + jj * 4);
            const float4 bb = *reinterpret_cast<const float4*>(b_out + n + jj * 4);
            v.x += vin.x + bb.x; v.y += vin.y + bb.y;
            v.z += vin.z + bb.z; v.w += vin.w + bb.w;
            *reinterpret_cast<float4*>(g_vf + row * CTD + n + jj * 4) = v;
        }
    }
}

// ---------------- 5) per-row cosine ----------------
__global__ void __launch_bounds__(256) cos_kernel(const float* __restrict__ teacher)
{
    int m = blockIdx.x, t = threadIdx.x;
    const float4* a = reinterpret_cast<const float4*>(g_vf + (size_t)m * CTD);
    const float4* b = reinterpret_cast<const float4*>(teacher + (size_t)m * CTD);
    float4 x = a[t], y = b[t];
    float dot = x.x*y.x + x.y*y.y + x.z*y.z + x.w*y.w;
    float n1  = x.x*x.x + x.y*x.y + x.z*x.z + x.w*x.w;
    float n2  = y.x*y.x + y.y*y.y + y.z*y.z + y.w*y.w;

    __shared__ float sd[8], s1[8], s2[8];
    float wd = warp_sum(dot), w1 = warp_sum(n1), w2 = warp_sum(n2);
    int w = t >> 5, lane = t & 31;
    if (lane == 0) { sd[w] = wd; s1[w] = w1; s2[w] = w2; }
    __syncthreads();
    if (t == 0) {
        float td = 0.f, t1 = 0.f, t2 = 0.f;
#pragma unroll
        for (int i = 0; i < 8; i++) { td += sd[i]; t1 += s1[i]; t2 += s2[i]; }
        float na = fmaxf(sqrtf(t1), COS_EPSF);
        float nb = fmaxf(sqrtf(t2), COS_EPSF);
        g_cos[m] = td / (na * nb);
    }
}

// ---------------- 6) final deterministic reduction ----------------
__global__ void __launch_bounds__(512) final_kernel(float* __restrict__ out)
{
    __shared__ float sh[512];
    int t = threadIdx.x;
    float s = 0.f;
    for (int i = t; i < MTOT; i += 512) s += g_cos[i];
    sh[t] = s;
    __syncthreads();
    for (int o = 256; o > 0; o >>= 1) {
        if (t < o) sh[t] += sh[t + o];
        __syncthreads();
    }
    if (t == 0) out[0] = 1.0f - sh[0] / (float)MTOT;
}

// ---------------- launch ----------------
extern "C" void kernel_launch(void* const* d_in, const int* in_sizes, int n_in,
                              void* d_out, int out_size)
{
    const float* features = (const float*)d_in[0];
    const float* teacher  = (const float*)d_in[1];
    const float* ln_scale = (const float*)d_in[2];
    const float* ln_bias  = (const float*)d_in[3];
    const float* w_norm   = (const float*)d_in[4];
    const float* w_in     = (const float*)d_in[5];
    const float* b_in     = (const float*)d_in[6];
    const float* w_out    = (const float*)d_in[7];
    const float* b_out    = (const float*)d_in[8];
    float* out = (float*)d_out;

    ln_kernel<<<MTOT * NLAYER, 256>>>(features, ln_scale, ln_bias);
    gemm1_kernel<<<dim3(CTD / 128, MTOT / 128, 8), 256>>>(features, w_norm, w_in, b_in);
    attn_kernel<<<MTOT, 128>>>();
    gemm2_kernel<<<dim3(CTD / 128, MTOT / 128), 256>>>(w_out, b_out);
    cos_kernel<<<MTOT, 256>>>(teacher);
    final_kernel<<<1, 512>>>(out);
}